// round 2
// baseline (speedup 1.0000x reference)
#include <cuda_runtime.h>
#include <mma.h>
#include <cstdint>

using namespace nvcuda;

namespace {
constexpr int NPTS = 262144;   // points
constexpr int CHN  = 96;       // channels
constexpr int KOFF = 27;       // 3x3x3 offsets
constexpr int MT   = 128;      // rows per block tile
constexpr int LDA  = 100;      // padded leading dim for gathered tile (multiple of 4)
constexpr int NTHR = 256;      // 8 warps
constexpr int QROW = CHN / 4;  // float4 chunks per row = 24
constexpr int SMEM_BYTES = (MT * LDA + CHN * CHN) * 4;  // 88064 B
}

// Intermediate activations (output of conv1+PReLU): 100 MB static scratch.
__device__ float g_scratch[(size_t)NPTS * CHN];

template<bool PASS2>
__global__ __launch_bounds__(NTHR, 2)
void conv_kernel(const float* __restrict__ fin,      // conv input  [N, CH]
                 const float* __restrict__ resid,    // residual (pass2) or nullptr
                 const int*   __restrict__ nidx,     // [K, N]
                 const int*   __restrict__ nmask,    // [K, N] bool delivered as int32
                 const float* __restrict__ W,        // [K, CH, CH]
                 const float* __restrict__ bias,     // [CH]
                 const float* __restrict__ alpha,    // [1]
                 float* __restrict__ out)            // [N, CH]
{
    extern __shared__ float smem[];
    float* sA = smem;               // [MT][LDA] gathered tile (tf32-rounded)
    float* sB = smem + MT * LDA;    // [CH][CH]  W[k] (tf32-rounded)

    const int tid  = threadIdx.x;
    const int warp = tid >> 5;
    const int row0 = blockIdx.x * MT;

    wmma::fragment<wmma::accumulator, 16, 16, 8, float> acc[6];
#pragma unroll
    for (int n = 0; n < 6; n++) wmma::fill_fragment(acc[n], 0.0f);

    for (int k = 0; k < KOFF; k++) {
        __syncthreads();  // previous iteration's MMA reads of sA/sB are done

        // ---- stage W[k] into sB (tf32-rounded) ----
        {
            const float4* Wk = reinterpret_cast<const float4*>(W + (size_t)k * CHN * CHN);
            float4* dB = reinterpret_cast<float4*>(sB);
            for (int i = tid; i < CHN * CHN / 4; i += NTHR) {
                float4 v = Wk[i];
                v.x = wmma::__float_to_tf32(v.x);
                v.y = wmma::__float_to_tf32(v.y);
                v.z = wmma::__float_to_tf32(v.z);
                v.w = wmma::__float_to_tf32(v.w);
                dB[i] = v;
            }
        }

        // ---- gather masked rows into sA (tf32-rounded) ----
        for (int i = tid; i < MT * QROW; i += NTHR) {
            const int row = i / QROW;
            const int q   = i % QROW;
            const int r   = row0 + row;
            const int nb  = nidx[(size_t)k * NPTS + r];
            const bool m  = nmask[(size_t)k * NPTS + r] != 0;
            float4 v = make_float4(0.f, 0.f, 0.f, 0.f);
            if (m) {
                v = *reinterpret_cast<const float4*>(fin + (size_t)nb * CHN + q * 4);
                v.x = wmma::__float_to_tf32(v.x);
                v.y = wmma::__float_to_tf32(v.y);
                v.z = wmma::__float_to_tf32(v.z);
                v.w = wmma::__float_to_tf32(v.w);
            }
            *reinterpret_cast<float4*>(sA + row * LDA + q * 4) = v;
        }
        __syncthreads();

        // ---- MMA: each warp does 16 rows x 96 cols x 96 K ----
        const float* aBase = sA + (warp * 16) * LDA;
#pragma unroll
        for (int kk = 0; kk < CHN / 8; kk++) {
            wmma::fragment<wmma::matrix_a, 16, 16, 8, wmma::precision::tf32, wmma::row_major> af;
            wmma::load_matrix_sync(af, aBase + kk * 8, LDA);
#pragma unroll
            for (int n = 0; n < 6; n++) {
                wmma::fragment<wmma::matrix_b, 16, 16, 8, wmma::precision::tf32, wmma::row_major> bf;
                wmma::load_matrix_sync(bf, sB + (kk * 8) * CHN + n * 16, CHN);
                wmma::mma_sync(acc[n], af, bf, acc[n]);
            }
        }
    }

    // ---- epilogue: park accumulators in sA, then bias/residual/PReLU/store ----
    __syncthreads();
    {
        float* oBase = sA + (warp * 16) * LDA;
#pragma unroll
        for (int n = 0; n < 6; n++)
            wmma::store_matrix_sync(oBase + n * 16, acc[n], LDA, wmma::mem_row_major);
    }
    __syncthreads();

    const float av = __ldg(alpha);
    for (int i = tid; i < MT * QROW; i += NTHR) {
        const int row = i / QROW;
        const int q   = i % QROW;
        const int r   = row0 + row;
        float4 v  = *reinterpret_cast<const float4*>(sA + row * LDA + q * 4);
        float4 bv = reinterpret_cast<const float4*>(bias)[q];
        v.x += bv.x; v.y += bv.y; v.z += bv.z; v.w += bv.w;
        if (PASS2) {
            float4 f = *reinterpret_cast<const float4*>(resid + (size_t)r * CHN + q * 4);
            v.x += f.x; v.y += f.y; v.z += f.z; v.w += f.w;
        }
        v.x = (v.x > 0.f) ? v.x : av * v.x;
        v.y = (v.y > 0.f) ? v.y : av * v.y;
        v.z = (v.z > 0.f) ? v.z : av * v.z;
        v.w = (v.w > 0.f) ? v.w : av * v.w;
        *reinterpret_cast<float4*>(out + (size_t)r * CHN + q * 4) = v;
    }
}

extern "C" void kernel_launch(void* const* d_in, const int* in_sizes, int n_in,
                              void* d_out, int out_size)
{
    const float*   feats = (const float*)d_in[0];
    const int*     nidx  = (const int*)d_in[1];
    const int*     nmask = (const int*)d_in[2];   // bool -> int32 in harness
    const float*   W1    = (const float*)d_in[3];
    const float*   b1    = (const float*)d_in[4];
    const float*   a1    = (const float*)d_in[5];
    const float*   W2    = (const float*)d_in[6];
    const float*   b2    = (const float*)d_in[7];
    const float*   a2    = (const float*)d_in[8];
    float* out = (float*)d_out;

    float* scratch = nullptr;
    cudaGetSymbolAddress((void**)&scratch, g_scratch);

    cudaFuncSetAttribute(conv_kernel<false>,
                         cudaFuncAttributeMaxDynamicSharedMemorySize, SMEM_BYTES);
    cudaFuncSetAttribute(conv_kernel<true>,
                         cudaFuncAttributeMaxDynamicSharedMemorySize, SMEM_BYTES);

    const int grid = NPTS / MT;  // 2048
    conv_kernel<false><<<grid, NTHR, SMEM_BYTES>>>(
        feats, nullptr, nidx, nmask, W1, b1, a1, scratch);
    conv_kernel<true><<<grid, NTHR, SMEM_BYTES>>>(
        scratch, feats, nidx, nmask, W2, b2, a2, out);
}

// round 5
// speedup vs baseline: 1.3771x; 1.3771x over previous
#include <cuda_runtime.h>
#include <mma.h>
#include <cstdint>

using namespace nvcuda;

namespace {
constexpr int NPTS = 262144;
constexpr int CHN  = 96;
constexpr int KOFF = 27;
constexpr int MT   = 256;        // rows per CTA tile
constexpr int NTHR = 256;        // 8 warps, 32 rows each
constexpr int LDA  = 100;        // padded ld (floats) for A tile
constexpr int BLD  = 100;        // padded ld (floats) for B tile
constexpr int QROW = CHN / 4;    // 24 float4 chunks per row
constexpr int SMEM_BYTES = (MT * LDA + CHN * BLD) * 4;  // 140800 B
}

__device__ float g_scratch[(size_t)NPTS * CHN];          // conv1 output (tf32-rounded)
__device__ float g_rfeats [(size_t)NPTS * CHN];          // feats, tf32-rounded
__device__ float g_wr     [2u * KOFF * CHN * CHN];       // W, tf32-rounded

// ---------------------------------------------------------------------------
__device__ __forceinline__ uint32_t smem_u32(const void* p) {
    uint32_t a;
    asm("{ .reg .u64 t; cvta.to.shared.u64 t, %1; cvt.u32.u64 %0, t; }" : "=r"(a) : "l"(p));
    return a;
}
__device__ __forceinline__ float to_tf32(float x) {
    float r; asm("cvt.rna.tf32.f32 %0, %1;" : "=f"(r) : "f"(x)); return r;
}
__device__ __forceinline__ void cp_async16(uint32_t dst, const void* src, int src_bytes) {
    asm volatile("cp.async.ca.shared.global [%0], [%1], 16, %2;"
                 :: "r"(dst), "l"(src), "r"(src_bytes) : "memory");
}
__device__ __forceinline__ void cp_commit_wait_all() {
    asm volatile("cp.async.commit_group;\n\tcp.async.wait_group 0;" ::: "memory");
}

// ---------------------------------------------------------------------------
// Prep: elementwise tf32 rounding (float4 vectorized)
// ---------------------------------------------------------------------------
__global__ void round_kernel(const float4* __restrict__ src, float4* __restrict__ dst, int n4) {
    for (int i = blockIdx.x * blockDim.x + threadIdx.x; i < n4; i += gridDim.x * blockDim.x) {
        float4 v = src[i];
        v.x = to_tf32(v.x); v.y = to_tf32(v.y); v.z = to_tf32(v.z); v.w = to_tf32(v.w);
        dst[i] = v;
    }
}

// ---------------------------------------------------------------------------
// Conv kernel: per CTA 256 rows, loop over 27 offsets, wmma tf32 16x16x8.
// ---------------------------------------------------------------------------
template<bool PASS2>
__global__ __launch_bounds__(NTHR, 1)
void conv_kernel(const float* __restrict__ fin,      // tf32-rounded conv input [N,CH]
                 const float* __restrict__ resid,    // original feats (pass2)
                 const int*   __restrict__ nidx,     // [K,N]
                 const int*   __restrict__ nmask,    // [K,N] (bool as int32)
                 const float* __restrict__ wr,       // tf32-rounded W [27][CH][CH]
                 const float* __restrict__ bias,
                 const float* __restrict__ alpha,
                 float* __restrict__ out)
{
    extern __shared__ float smem[];
    float* sA = smem;                 // [MT][LDA]
    float* sB = smem + MT * LDA;      // [CH][BLD]
    const uint32_t sAu = smem_u32(sA);
    const uint32_t sBu = smem_u32(sB);

    const int tid  = threadIdx.x;
    const int warp = tid >> 5;
    const int row0 = blockIdx.x * MT;

    wmma::fragment<wmma::accumulator, 16, 16, 8, float> acc[12];
#pragma unroll
    for (int i = 0; i < 12; i++) wmma::fill_fragment(acc[i], 0.0f);

    for (int k = 0; k < KOFF; k++) {
        // ---- stage A: one row per thread via cp.async (zfill when masked) ----
        {
            const int r  = row0 + tid;
            const int nb = nidx [(size_t)k * NPTS + r];
            const int m  = nmask[(size_t)k * NPTS + r];
            const int sz = m ? 16 : 0;
            const char* src = (const char*)(fin + (size_t)nb * CHN);
            const uint32_t dst = sAu + tid * (LDA * 4);
#pragma unroll
            for (int q = 0; q < QROW; q++)
                cp_async16(dst + q * 16, src + q * 16, sz);
        }
        // ---- stage B: W[k] rows into padded smem ----
        {
            const char* wk = (const char*)(wr + (size_t)k * CHN * CHN);
#pragma unroll
            for (int j = 0; j < 9; j++) {
                const int i = tid + j * NTHR;           // 0..2303
                const int row = i / QROW, q = i % QROW;
                cp_async16(sBu + row * (BLD * 4) + q * 16, wk + row * (CHN * 4) + q * 16, 16);
            }
        }
        cp_commit_wait_all();
        __syncthreads();

        // ---- MMA: warp tile 32 rows x 96 cols ----
        const float* aBase = sA + (warp * 32) * LDA;
#pragma unroll
        for (int kk = 0; kk < CHN / 8; kk++) {
            wmma::fragment<wmma::matrix_a, 16, 16, 8, wmma::precision::tf32, wmma::row_major> a0, a1;
            wmma::load_matrix_sync(a0, aBase + kk * 8, LDA);
            wmma::load_matrix_sync(a1, aBase + 16 * LDA + kk * 8, LDA);
#pragma unroll
            for (int n = 0; n < 6; n++) {
                wmma::fragment<wmma::matrix_b, 16, 16, 8, wmma::precision::tf32, wmma::row_major> bf;
                wmma::load_matrix_sync(bf, sB + (kk * 8) * BLD + n * 16, BLD);
                wmma::mma_sync(acc[n],     a0, bf, acc[n]);
                wmma::mma_sync(acc[6 + n], a1, bf, acc[6 + n]);
            }
        }
        __syncthreads();   // MMA reads done before next k overwrites sA/sB
    }

    // ---- epilogue: park accumulators in sA, then bias/residual/PReLU ----
    {
        float* oBase = sA + (warp * 32) * LDA;
#pragma unroll
        for (int n = 0; n < 6; n++) {
            wmma::store_matrix_sync(oBase + n * 16,            acc[n],     LDA, wmma::mem_row_major);
            wmma::store_matrix_sync(oBase + 16 * LDA + n * 16, acc[6 + n], LDA, wmma::mem_row_major);
        }
    }
    __syncthreads();

    const float av = __ldg(alpha);
#pragma unroll 1
    for (int i = tid; i < MT * QROW; i += NTHR) {
        const int row = i / QROW;
        const int q   = i % QROW;
        const int r   = row0 + row;
        float4 v  = *reinterpret_cast<const float4*>(sA + row * LDA + q * 4);
        float4 bv = reinterpret_cast<const float4*>(bias)[q];
        v.x += bv.x; v.y += bv.y; v.z += bv.z; v.w += bv.w;
        if (PASS2) {
            float4 f = *reinterpret_cast<const float4*>(resid + (size_t)r * CHN + q * 4);
            v.x += f.x; v.y += f.y; v.z += f.z; v.w += f.w;
        }
        v.x = (v.x > 0.f) ? v.x : av * v.x;
        v.y = (v.y > 0.f) ? v.y : av * v.y;
        v.z = (v.z > 0.f) ? v.z : av * v.z;
        v.w = (v.w > 0.f) ? v.w : av * v.w;
        if (!PASS2) {   // conv2 will consume this as tf32 operands: round now
            v.x = to_tf32(v.x); v.y = to_tf32(v.y);
            v.z = to_tf32(v.z); v.w = to_tf32(v.w);
        }
        *reinterpret_cast<float4*>(out + (size_t)r * CHN + q * 4) = v;
    }
}

// ---------------------------------------------------------------------------
extern "C" void kernel_launch(void* const* d_in, const int* in_sizes, int n_in,
                              void* d_out, int out_size)
{
    const float* feats = (const float*)d_in[0];
    const int*   nidx  = (const int*)d_in[1];
    const int*   nmask = (const int*)d_in[2];
    const float* W1    = (const float*)d_in[3];
    const float* b1    = (const float*)d_in[4];
    const float* a1    = (const float*)d_in[5];
    const float* W2    = (const float*)d_in[6];
    const float* b2    = (const float*)d_in[7];
    const float* a2    = (const float*)d_in[8];
    float* out = (float*)d_out;

    float *scratch = nullptr, *rfeats = nullptr, *wr = nullptr;
    cudaGetSymbolAddress((void**)&scratch, g_scratch);
    cudaGetSymbolAddress((void**)&rfeats,  g_rfeats);
    cudaGetSymbolAddress((void**)&wr,      g_wr);

    cudaFuncSetAttribute(conv_kernel<false>,
                         cudaFuncAttributeMaxDynamicSharedMemorySize, SMEM_BYTES);
    cudaFuncSetAttribute(conv_kernel<true>,
                         cudaFuncAttributeMaxDynamicSharedMemorySize, SMEM_BYTES);

    const int WN4 = KOFF * CHN * CHN / 4;             // 62208
    round_kernel<<<64, 256>>>((const float4*)W1, (float4*)wr, WN4);
    round_kernel<<<64, 256>>>((const float4*)W2, (float4*)(wr + (size_t)KOFF * CHN * CHN), WN4);
    round_kernel<<<2048, 256>>>((const float4*)feats, (float4*)rfeats, NPTS * CHN / 4);

    const int grid = NPTS / MT;  // 1024
    conv_kernel<false><<<grid, NTHR, SMEM_BYTES>>>(
        rfeats, nullptr, nidx, nmask, wr, b1, a1, scratch);
    conv_kernel<true><<<grid, NTHR, SMEM_BYTES>>>(
        scratch, feats, nidx, nmask, wr + (size_t)KOFF * CHN * CHN, b2, a2, out);
}